// round 8
// baseline (speedup 1.0000x reference)
#include <cuda_runtime.h>
#include <cuda_bf16.h>

#define GD 128
#define RB 66                         // brick coords 0..65 cover x0 in [-2..128]
#define BRICKS (RB * RB * RB)         // 287,496 bricks per replica
#define TOTAL_BRICKS (8 * BRICKS)     // 8 parity replicas
// Each brick = 2x2x2 cells as bf16 = 16 bytes.
__device__ uint4 g_rep[TOTAL_BRICKS]; // 36.8 MB, zero-initialized at load;
                                      // zero_kernel restores invariant per call.

__device__ __forceinline__ unsigned pack_bf16x2(float lo, float hi) {
    unsigned u;
    asm("cvt.rn.bf16x2.f32 %0, %1, %2;" : "=r"(u) : "f"(hi), "f"(lo));
    return u;
}

__device__ __forceinline__ void red_add_v4_bf16x2(void* addr, unsigned a,
                                                  unsigned b, unsigned c,
                                                  unsigned d) {
    asm volatile("red.global.add.noftz.v4.bf16x2 [%0], {%1, %2, %3, %4};"
                 :: "l"(addr), "r"(a), "r"(b), "r"(c), "r"(d) : "memory");
}

// ---------------------------------------------------------------------------
// One splat = ONE v4.bf16x2 red: replica (x0&1,y0&1,z0&1) makes the 2x2x2
// corner cube one aligned 16B brick. Lane idx = lz*4 + ly*2 + lx.
// ---------------------------------------------------------------------------
__device__ __forceinline__ void splat_one(float cx, float cy, float cz,
                                          float sign) {
    const float x = fmaf(cx, 64.0f, 63.5f);   // ((c+1)*128-1)/2
    const float y = fmaf(cy, 64.0f, 63.5f);
    const float z = fmaf(cz, 64.0f, 63.5f);

    const float x0f = floorf(x), y0f = floorf(y), z0f = floorf(z);
    const float fx = x - x0f, fy = y - y0f, fz = z - z0f;
    int x0 = (int)x0f, y0 = (int)y0f, z0 = (int)z0f;
    // Far-out points clamp into the padded range; OOB corners land in padding
    // slots the huber gather never reads.
    x0 = max(-2, min(128, x0));
    y0 = max(-2, min(128, y0));
    z0 = max(-2, min(128, z0));

    const float wx0 = 1.0f - fx, wx1 = fx;
    const float wy0 = 1.0f - fy, wy1 = fy;
    const float wz0 = (1.0f - fz) * sign, wz1 = fz * sign;

    const int sx = x0 & 1, sy = y0 & 1, sz = z0 & 1;
    const int bx = (x0 + sx + 2) >> 1;
    const int by = (y0 + sy + 2) >> 1;
    const int bz = (z0 + sz + 2) >> 1;
    const int rep = (sz << 2) | (sy << 1) | sx;

    uint4* addr = g_rep + (size_t)rep * BRICKS
                + ((size_t)bz * RB + by) * RB + bx;

    const float a00 = wx0 * wy0, a10 = wx1 * wy0;
    const float a01 = wx0 * wy1, a11 = wx1 * wy1;

    red_add_v4_bf16x2(addr,
        pack_bf16x2(a00 * wz0, a10 * wz0),
        pack_bf16x2(a01 * wz0, a11 * wz0),
        pack_bf16x2(a00 * wz1, a10 * wz1),
        pack_bf16x2(a01 * wz1, a11 * wz1));
}

// ---------------------------------------------------------------------------
// Splat: ONE point per thread (proven best occupancy/latency-hiding shape).
// ---------------------------------------------------------------------------
__global__ void splat_kernel(const float* __restrict__ pred,
                             const float* __restrict__ gt,
                             const float* __restrict__ coords,
                             int N, float* __restrict__ out) {
    const int p = blockIdx.x * blockDim.x + threadIdx.x;
    if (p == 0) *out = 0.f;      // huber (next kernel) accumulates into out
    if (p >= N) return;

    const float cx = coords[3 * p + 0];
    const float cy = coords[3 * p + 1];
    const float cz = coords[3 * p + 2];
    const float px = pred[3 * p + 0];
    const float py = pred[3 * p + 1];
    const float pz = pred[3 * p + 2];
    const float gx = gt[3 * p + 0];
    const float gy = gt[3 * p + 1];
    const float gz = gt[3 * p + 2];

    splat_one(cx + px, cy + py, cz + pz,  1.0f);
    splat_one(cx + gx, cy + gy, cz + gz, -1.0f);
}

// ---------------------------------------------------------------------------
// Huber: per-cell gather (consecutive lanes -> consecutive cells -> coalesced
// 2B loads). 4 cells/thread strided; 32 independent loads (MLP 32).
// PDL: blocks launch during splat's drain; sync before first grid read.
// ---------------------------------------------------------------------------
#define HUB_BLOCKS 2048
#define HUB_THREADS 256
#define HUB_STRIDE (HUB_BLOCKS * HUB_THREADS)   // 524,288; x4 = 2,097,152 cells

__global__ void huber_kernel(float* __restrict__ out) {
    const __nv_bfloat16* __restrict__ gb =
        reinterpret_cast<const __nv_bfloat16*>(g_rep);
    const int t = blockIdx.x * HUB_THREADS + threadIdx.x;

    cudaGridDependencySynchronize();   // wait for splat's reds to be visible

    float s = 0.f;
    #pragma unroll
    for (int g = 0; g < 4; ++g) {
        const int cell = t + g * HUB_STRIDE;
        const int xx = cell & 127;
        const int yy = (cell >> 7) & 127;
        const int zz = cell >> 14;
        float v = 0.f;
        #pragma unroll
        for (int rep = 0; rep < 8; ++rep) {
            const int sx = rep & 1, sy = (rep >> 1) & 1, sz = rep >> 2;
            const int lx = (xx ^ sx) & 1;
            const int ly = (yy ^ sy) & 1;
            const int lz = (zz ^ sz) & 1;
            const int bx = (xx - lx + sx + 2) >> 1;
            const int by = (yy - ly + sy + 2) >> 1;
            const int bz = (zz - lz + sz + 2) >> 1;
            const size_t brick = (size_t)rep * BRICKS
                               + ((size_t)bz * RB + by) * RB + bx;
            v += __bfloat162float(gb[brick * 8 + (lz << 2) + (ly << 1) + lx]);
        }
        const float a = fabsf(v);
        s += (a <= 1.f) ? 0.5f * v * v : a - 0.5f;
    }

    #pragma unroll
    for (int o = 16; o; o >>= 1) s += __shfl_xor_sync(0xFFFFFFFFu, s, o);

    __shared__ float smem[8];
    const int lane = threadIdx.x & 31;
    const int warp = threadIdx.x >> 5;
    if (lane == 0) smem[warp] = s;
    __syncthreads();

    if (warp == 0) {
        s = (lane < (HUB_THREADS >> 5)) ? smem[lane] : 0.f;
        #pragma unroll
        for (int o = 4; o; o >>= 1) s += __shfl_xor_sync(0xFFFFFFFFu, s, o);
        if (lane == 0) atomicAdd(out, s);
    }
}

// ---------------------------------------------------------------------------
// Zero the replica bricks (4 bricks = 64B per thread).
// PDL: blocks launch during huber's drain; sync before clobbering the grid.
// ---------------------------------------------------------------------------
__global__ void zero_kernel() {
    const int i = (blockIdx.x * blockDim.x + threadIdx.x) * 4;

    cudaGridDependencySynchronize();   // wait until huber is done reading

    if (i + 4 <= TOTAL_BRICKS) {
        const uint4 z = make_uint4(0u, 0u, 0u, 0u);
        g_rep[i] = z; g_rep[i+1] = z; g_rep[i+2] = z; g_rep[i+3] = z;
    } else {
        for (int k = i; k < TOTAL_BRICKS; ++k)
            g_rep[k] = make_uint4(0u, 0u, 0u, 0u);
    }
}

// ---------------------------------------------------------------------------
// Launch: splat -> huber (PDL) -> zero (PDL)
// ---------------------------------------------------------------------------
extern "C" void kernel_launch(void* const* d_in, const int* in_sizes, int n_in,
                              void* d_out, int out_size) {
    const float* pred   = (const float*)d_in[0];  // registration_pred [1,N,3]
    const float* gt     = (const float*)d_in[1];  // registration_gt   [1,N,3]
    const float* coords = (const float*)d_in[2];  // coords            [1,N,3]
    float* out = (float*)d_out;

    const int N = in_sizes[0] / 3;

    {   // splat: one thread per point (pred +1, gt -1); also zeroes *out
        const int threads = 256;
        splat_kernel<<<(N + threads - 1) / threads, threads>>>(
            pred, gt, coords, N, out);
    }

    cudaLaunchAttribute pdl[1];
    pdl[0].id = cudaLaunchAttributeProgrammaticStreamSerialization;
    pdl[0].val.programmaticStreamSerializationAllowed = 1;

    {   // huber gather + reduction (PDL overlap with splat drain)
        cudaLaunchConfig_t cfg = {};
        cfg.gridDim = dim3(HUB_BLOCKS, 1, 1);
        cfg.blockDim = dim3(HUB_THREADS, 1, 1);
        cfg.attrs = pdl;
        cfg.numAttrs = 1;
        cudaLaunchKernelEx(&cfg, huber_kernel, out);
    }
    {   // reset replica bricks (PDL overlap with huber drain)
        const int threads = 256;
        const int nt = (TOTAL_BRICKS + 3) / 4;
        cudaLaunchConfig_t cfg = {};
        cfg.gridDim = dim3((nt + threads - 1) / threads, 1, 1);
        cfg.blockDim = dim3(threads, 1, 1);
        cfg.attrs = pdl;
        cfg.numAttrs = 1;
        cudaLaunchKernelEx(&cfg, zero_kernel);
    }
}

// round 10
// speedup vs baseline: 1.2334x; 1.2334x over previous
#include <cuda_runtime.h>
#include <cuda_bf16.h>
#include <cooperative_groups.h>

namespace cg = cooperative_groups;

#define GD 128
#define RB 66                         // brick coords 0..65 cover x0 in [-2..128]
#define BRICKS (RB * RB * RB)         // 287,496 bricks per replica
#define TOTAL_BRICKS (8 * BRICKS)     // 8 parity replicas
#define CELLS (GD * GD * GD)
// Each brick = 2x2x2 cells as bf16 = 16 bytes.
__device__ uint4 g_rep[TOTAL_BRICKS]; // 36.8 MB, zero-initialized at load;
                                      // phase 3 restores the invariant.

__device__ __forceinline__ unsigned pack_bf16x2(float lo, float hi) {
    unsigned u;
    asm("cvt.rn.bf16x2.f32 %0, %1, %2;" : "=r"(u) : "f"(hi), "f"(lo));
    return u;
}

__device__ __forceinline__ void red_add_v4_bf16x2(void* addr, unsigned a,
                                                  unsigned b, unsigned c,
                                                  unsigned d) {
    asm volatile("red.global.add.noftz.v4.bf16x2 [%0], {%1, %2, %3, %4};"
                 :: "l"(addr), "r"(a), "r"(b), "r"(c), "r"(d) : "memory");
}

// ---------------------------------------------------------------------------
// One splat = ONE v4.bf16x2 red: replica (x0&1,y0&1,z0&1) makes the 2x2x2
// corner cube one aligned 16B brick. Lane idx = lz*4 + ly*2 + lx.
// ---------------------------------------------------------------------------
__device__ __forceinline__ void splat_one(float cx, float cy, float cz,
                                          float sign) {
    const float x = fmaf(cx, 64.0f, 63.5f);   // ((c+1)*128-1)/2
    const float y = fmaf(cy, 64.0f, 63.5f);
    const float z = fmaf(cz, 64.0f, 63.5f);

    const float x0f = floorf(x), y0f = floorf(y), z0f = floorf(z);
    const float fx = x - x0f, fy = y - y0f, fz = z - z0f;
    int x0 = (int)x0f, y0 = (int)y0f, z0 = (int)z0f;
    // Far-out points clamp into the padded range; OOB corners land in padding
    // slots the huber gather never reads.
    x0 = max(-2, min(128, x0));
    y0 = max(-2, min(128, y0));
    z0 = max(-2, min(128, z0));

    const float wx0 = 1.0f - fx, wx1 = fx;
    const float wy0 = 1.0f - fy, wy1 = fy;
    const float wz0 = (1.0f - fz) * sign, wz1 = fz * sign;

    const int sx = x0 & 1, sy = y0 & 1, sz = z0 & 1;
    const int bx = (x0 + sx + 2) >> 1;
    const int by = (y0 + sy + 2) >> 1;
    const int bz = (z0 + sz + 2) >> 1;
    const int rep = (sz << 2) | (sy << 1) | sx;

    uint4* addr = g_rep + (size_t)rep * BRICKS
                + ((size_t)bz * RB + by) * RB + bx;

    const float a00 = wx0 * wy0, a10 = wx1 * wy0;
    const float a01 = wx0 * wy1, a11 = wx1 * wy1;

    red_add_v4_bf16x2(addr,
        pack_bf16x2(a00 * wz0, a10 * wz0),
        pack_bf16x2(a01 * wz0, a11 * wz0),
        pack_bf16x2(a00 * wz1, a10 * wz1),
        pack_bf16x2(a01 * wz1, a11 * wz1));
}

__device__ __forceinline__ float huber_cell(const __nv_bfloat16* __restrict__ gb,
                                            int cell) {
    const int xx = cell & 127;
    const int yy = (cell >> 7) & 127;
    const int zz = cell >> 14;
    float v = 0.f;
    #pragma unroll
    for (int rep = 0; rep < 8; ++rep) {
        const int sx = rep & 1, sy = (rep >> 1) & 1, sz = rep >> 2;
        const int lx = (xx ^ sx) & 1;
        const int ly = (yy ^ sy) & 1;
        const int lz = (zz ^ sz) & 1;
        const int bx = (xx - lx + sx + 2) >> 1;
        const int by = (yy - ly + sy + 2) >> 1;
        const int bz = (zz - lz + sz + 2) >> 1;
        const size_t brick = (size_t)rep * BRICKS
                           + ((size_t)bz * RB + by) * RB + bx;
        v += __bfloat162float(gb[brick * 8 + (lz << 2) + (ly << 1) + lx]);
    }
    const float a = fabsf(v);
    return (a <= 1.f) ? 0.5f * v * v : a - 0.5f;
}

// ---------------------------------------------------------------------------
// Fused cooperative kernel: splat -> grid.sync -> huber -> grid.sync -> zero.
// ---------------------------------------------------------------------------
__global__ void __launch_bounds__(256)
fused_kernel(const float* __restrict__ pred,
             const float* __restrict__ gt,
             const float* __restrict__ coords,
             int N, float* __restrict__ out) {
    cg::grid_group grid = cg::this_grid();
    const int tid = blockIdx.x * blockDim.x + threadIdx.x;
    const int stride = gridDim.x * blockDim.x;

    if (tid == 0) *out = 0.f;

    // ---- Phase 1: splat (pred +1, gt -1), one point per iteration ----
    for (int p = tid; p < N; p += stride) {
        const float cx = coords[3 * p + 0];
        const float cy = coords[3 * p + 1];
        const float cz = coords[3 * p + 2];
        const float px = pred[3 * p + 0];
        const float py = pred[3 * p + 1];
        const float pz = pred[3 * p + 2];
        const float gx = gt[3 * p + 0];
        const float gy = gt[3 * p + 1];
        const float gz = gt[3 * p + 2];
        splat_one(cx + px, cy + py, cz + pz,  1.0f);
        splat_one(cx + gx, cy + gy, cz + gz, -1.0f);
    }

    grid.sync();

    // ---- Phase 2: huber gather + reduction (4 cells per outer iter, MLP) --
    const __nv_bfloat16* __restrict__ gb =
        reinterpret_cast<const __nv_bfloat16*>(g_rep);
    float s = 0.f;
    for (int c0 = tid; c0 < CELLS; c0 += 4 * stride) {
        const int c1 = c0 + stride, c2 = c0 + 2 * stride, c3 = c0 + 3 * stride;
        s += huber_cell(gb, c0);
        if (c1 < CELLS) s += huber_cell(gb, c1);
        if (c2 < CELLS) s += huber_cell(gb, c2);
        if (c3 < CELLS) s += huber_cell(gb, c3);
    }

    #pragma unroll
    for (int o = 16; o; o >>= 1) s += __shfl_xor_sync(0xFFFFFFFFu, s, o);

    __shared__ float smem[8];
    const int lane = threadIdx.x & 31;
    const int warp = threadIdx.x >> 5;
    if (lane == 0) smem[warp] = s;
    __syncthreads();
    if (warp == 0) {
        s = (lane < 8) ? smem[lane] : 0.f;
        #pragma unroll
        for (int o = 4; o; o >>= 1) s += __shfl_xor_sync(0xFFFFFFFFu, s, o);
        if (lane == 0) atomicAdd(out, s);
    }

    grid.sync();

    // ---- Phase 3: zero the replica bricks for the next replay -------------
    const uint4 zed = make_uint4(0u, 0u, 0u, 0u);
    for (int i = tid; i < TOTAL_BRICKS; i += stride)
        g_rep[i] = zed;
}

// ---------------------------------------------------------------------------
// Launch: single cooperative kernel.
// ---------------------------------------------------------------------------
extern "C" void kernel_launch(void* const* d_in, const int* in_sizes, int n_in,
                              void* d_out, int out_size) {
    const float* pred   = (const float*)d_in[0];  // registration_pred [1,N,3]
    const float* gt     = (const float*)d_in[1];  // registration_gt   [1,N,3]
    const float* coords = (const float*)d_in[2];  // coords            [1,N,3]
    float* out = (float*)d_out;
    int N = in_sizes[0] / 3;

    int dev = 0;
    cudaGetDevice(&dev);
    int sms = 0;
    cudaDeviceGetAttribute(&sms, cudaDevAttrMultiProcessorCount, dev);
    int per_sm = 0;
    cudaOccupancyMaxActiveBlocksPerMultiprocessor(&per_sm, fused_kernel, 256, 0);
    if (per_sm < 1) per_sm = 1;
    int blocks = sms * per_sm;

    cudaLaunchAttribute attrs[1];
    attrs[0].id = cudaLaunchAttributeCooperative;
    attrs[0].val.cooperative = 1;

    cudaLaunchConfig_t cfg = {};
    cfg.gridDim = dim3((unsigned)blocks, 1, 1);
    cfg.blockDim = dim3(256, 1, 1);
    cfg.dynamicSmemBytes = 0;
    cfg.attrs = attrs;
    cfg.numAttrs = 1;

    cudaLaunchKernelEx(&cfg, fused_kernel, pred, gt, coords, N, out);
}